// round 1
// baseline (speedup 1.0000x reference)
#include <cuda_runtime.h>
#include <cuda_bf16.h>
#include <math.h>

#define POOL 7
#define MAX_ROIS 2048

// Precomputed per-ROI sampling coordinates (allocation-free scratch).
__device__ int   g_y0[MAX_ROIS * POOL];
__device__ int   g_y1[MAX_ROIS * POOL];
__device__ int   g_x0[MAX_ROIS * POOL];
__device__ int   g_x1[MAX_ROIS * POOL];
__device__ float g_dy[MAX_ROIS * POOL];
__device__ float g_dx[MAX_ROIS * POOL];

// Robustly read the stride scalar regardless of dtype (int32/int64 little-endian
// both give 16 at offset 0; float32 falls back to float interpretation).
__device__ __forceinline__ float read_stride(const void* p) {
    int iv = *(const int*)p;
    if (iv >= 1 && iv <= 65536) return (float)iv;
    float fv = *(const float*)p;
    return fv;
}

__global__ void roi_precompute_kernel(const float* __restrict__ rois,
                                      const void* __restrict__ stride_p,
                                      int N) {
    int n = blockIdx.x * blockDim.x + threadIdx.x;
    if (n >= N) return;
    float s = read_stride(stride_p);

    // r = (rois / stride).astype(int32)  (values nonnegative -> trunc == floor)
    int ymin = (int)(rois[4 * n + 0] / s);
    int xmin = (int)(rois[4 * n + 1] / s);
    int ymax = (int)(rois[4 * n + 2] / s);
    int xmax = (int)(rois[4 * n + 3] / s);

    // y axis
    {
        float in_size = (float)(ymax - ymin + 1);
        float scale = in_size / (float)POOL;
        int span = ymax - ymin;
#pragma unroll
        for (int j = 0; j < POOL; j++) {
            float src = (float)j * scale;
            int i0 = (int)floorf(src);
            float frac = src - (float)i0;
            int i1 = min(i0 + 1, span);
            g_y0[n * POOL + j] = ymin + i0;
            g_y1[n * POOL + j] = ymin + i1;
            g_dy[n * POOL + j] = frac;
        }
    }
    // x axis
    {
        float in_size = (float)(xmax - xmin + 1);
        float scale = in_size / (float)POOL;
        int span = xmax - xmin;
#pragma unroll
        for (int j = 0; j < POOL; j++) {
            float src = (float)j * scale;
            int i0 = (int)floorf(src);
            float frac = src - (float)i0;
            int i1 = min(i0 + 1, span);
            g_x0[n * POOL + j] = xmin + i0;
            g_x1[n * POOL + j] = xmin + i1;
            g_dx[n * POOL + j] = frac;
        }
    }
}

// One block per (roi, py, px); 256 threads x float4 covers C=1024.
__global__ void __launch_bounds__(256)
roi_pool_kernel(const float* __restrict__ feat,
                float* __restrict__ out,
                int W, int C4) {
    int p = blockIdx.x;            // 0..48
    int n = blockIdx.y;            // roi
    int py = p / POOL;
    int px = p - py * POOL;

    int iy = n * POOL + py;
    int ix = n * POOL + px;
    int y0 = g_y0[iy], y1 = g_y1[iy];
    int x0 = g_x0[ix], x1 = g_x1[ix];
    float dy = g_dy[iy], dx = g_dx[ix];

    const float4* __restrict__ f = (const float4*)feat;
    float4* __restrict__ o = (float4*)out;

    int b00 = (y0 * W + x0) * C4;
    int b01 = (y0 * W + x1) * C4;
    int b10 = (y1 * W + x0) * C4;
    int b11 = (y1 * W + x1) * C4;
    int obase = (n * (POOL * POOL) + p) * C4;

    for (int c = threadIdx.x; c < C4; c += blockDim.x) {
        float4 f00 = f[b00 + c];
        float4 f01 = f[b01 + c];
        float4 f10 = f[b10 + c];
        float4 f11 = f[b11 + c];

        float4 r;
        {
            float top = f00.x + (f01.x - f00.x) * dx;
            float bot = f10.x + (f11.x - f10.x) * dx;
            r.x = top + (bot - top) * dy;
        }
        {
            float top = f00.y + (f01.y - f00.y) * dx;
            float bot = f10.y + (f11.y - f10.y) * dx;
            r.y = top + (bot - top) * dy;
        }
        {
            float top = f00.z + (f01.z - f00.z) * dx;
            float bot = f10.z + (f11.z - f10.z) * dx;
            r.z = top + (bot - top) * dy;
        }
        {
            float top = f00.w + (f01.w - f00.w) * dx;
            float bot = f10.w + (f11.w - f10.w) * dx;
            r.w = top + (bot - top) * dy;
        }
        o[obase + c] = r;
    }
}

extern "C" void kernel_launch(void* const* d_in, const int* in_sizes, int n_in,
                              void* d_out, int out_size) {
    const float* feat  = (const float*)d_in[0];   // (1, H, W, C) fp32
    const float* rois  = (const float*)d_in[1];   // (N, 4) fp32
    const void*  strid = d_in[2];                 // scalar

    int N = in_sizes[1] / 4;
    int C = out_size / (N * POOL * POOL);         // 1024
    int HW = in_sizes[0] / C;                     // 4096
    // assume square feature map
    int W = 1;
    while (W * W < HW) W <<= 1;                   // 64 for HW=4096
    if (W * W != HW) {
        // non-power-of-two fallback
        W = (int)(sqrtf((float)HW) + 0.5f);
    }

    roi_precompute_kernel<<<(N + 255) / 256, 256>>>(rois, strid, N);

    dim3 grid(POOL * POOL, N);
    roi_pool_kernel<<<grid, 256>>>(feat, (float*)d_out, W, C / 4);
}

// round 2
// speedup vs baseline: 1.3195x; 1.3195x over previous
#include <cuda_runtime.h>
#include <cuda_bf16.h>
#include <math.h>

#define POOL 7

// Robustly read the stride scalar regardless of dtype (int32/int64 little-endian
// both give the int at offset 0; float32 falls back to float interpretation).
__device__ __forceinline__ float read_stride(const void* p) {
    int iv = *(const int*)p;
    if (iv >= 1 && iv <= 65536) return (float)iv;
    return *(const float*)p;
}

// One block per (roi, py). 256 threads; each thread owns one float4 channel
// chunk (C4 = C/4 = 256) and iterates px = 0..6 with a sliding 2-column cache
// so overlapping bilinear taps are loaded once (~2*K loads instead of 28).
__global__ void __launch_bounds__(256)
roi_pool_kernel(const float* __restrict__ feat,
                const float* __restrict__ rois,
                const void* __restrict__ stride_p,
                float* __restrict__ out,
                int W, int C4) {
    const int py = blockIdx.x;     // 0..6
    const int n  = blockIdx.y;     // roi index

    // ---- uniform per-block coordinate math (replaces the precompute kernel) ----
    const float s = read_stride(stride_p);
    const int ymin = (int)(rois[4 * n + 0] / s);
    const int xmin = (int)(rois[4 * n + 1] / s);
    const int ymax = (int)(rois[4 * n + 2] / s);
    const int xmax = (int)(rois[4 * n + 3] / s);

    // y axis for this py
    const int   spany = ymax - ymin;
    const float sy    = (float)(spany + 1) / (float)POOL;
    const float srcy  = (float)py * sy;
    const int   iy0   = (int)floorf(srcy);
    const float dy    = srcy - (float)iy0;
    const int   iy1   = min(iy0 + 1, spany);
    const int   y0    = ymin + iy0;
    const int   y1    = ymin + iy1;

    // x axis params
    const int   spanx = xmax - xmin;
    const float sx    = (float)(spanx + 1) / (float)POOL;

    const float4* __restrict__ f = (const float4*)feat;
    const float4* __restrict__ row0 = f + (size_t)(y0 * W) * C4;
    const float4* __restrict__ row1 = f + (size_t)(y1 * W) * C4;
    float4* __restrict__ o = (float4*)out + ((size_t)n * (POOL * POOL) + (size_t)py * POOL) * C4;

    for (int c = threadIdx.x; c < C4; c += blockDim.x) {
        // sliding cache: columns cA (usually x0) and cB (usually x1 = cA+1)
        int cA = -1, cB = -1;
        float4 a0, a1, b0, b1;   // (row0,row1) values at column cA / cB

#pragma unroll
        for (int px = 0; px < POOL; ++px) {
            const float srcx = (float)px * sx;
            const int   ix0  = (int)floorf(srcx);
            const float dx   = srcx - (float)ix0;
            const int   ix1  = min(ix0 + 1, spanx);
            const int   nx0  = xmin + ix0;
            const int   nx1  = xmin + ix1;

            if (nx0 != cA) {                 // warp-uniform branches
                if (nx0 == cB) { a0 = b0; a1 = b1; }
                else {
                    a0 = row0[(size_t)nx0 * C4 + c];
                    a1 = row1[(size_t)nx0 * C4 + c];
                }
                cA = nx0;
            }
            if (nx1 != cB) {
                if (nx1 == cA) { b0 = a0; b1 = a1; }
                else {
                    b0 = row0[(size_t)nx1 * C4 + c];
                    b1 = row1[(size_t)nx1 * C4 + c];
                }
                cB = nx1;
            }

            float4 r;
            {
                float top = a0.x + (b0.x - a0.x) * dx;
                float bot = a1.x + (b1.x - a1.x) * dx;
                r.x = top + (bot - top) * dy;
            }
            {
                float top = a0.y + (b0.y - a0.y) * dx;
                float bot = a1.y + (b1.y - a1.y) * dx;
                r.y = top + (bot - top) * dy;
            }
            {
                float top = a0.z + (b0.z - a0.z) * dx;
                float bot = a1.z + (b1.z - a1.z) * dx;
                r.z = top + (bot - top) * dy;
            }
            {
                float top = a0.w + (b0.w - a0.w) * dx;
                float bot = a1.w + (b1.w - a1.w) * dx;
                r.w = top + (bot - top) * dy;
            }
            o[(size_t)px * C4 + c] = r;
        }
    }
}

extern "C" void kernel_launch(void* const* d_in, const int* in_sizes, int n_in,
                              void* d_out, int out_size) {
    const float* feat  = (const float*)d_in[0];   // (1, H, W, C) fp32
    const float* rois  = (const float*)d_in[1];   // (N, 4) fp32
    const void*  strid = d_in[2];                 // scalar

    int N = in_sizes[1] / 4;
    int C = out_size / (N * POOL * POOL);         // 1024
    int HW = in_sizes[0] / C;                     // 4096
    int W = 1;
    while (W * W < HW) W <<= 1;                   // 64 for HW=4096
    if (W * W != HW) {
        W = (int)(sqrtf((float)HW) + 0.5f);       // non-pow2 fallback
    }

    dim3 grid(POOL, N);
    roi_pool_kernel<<<grid, 256>>>(feat, rois, strid, (float*)d_out, W, C / 4);
}

// round 3
// speedup vs baseline: 1.3902x; 1.0536x over previous
#include <cuda_runtime.h>
#include <cuda_bf16.h>
#include <math.h>

#define POOL 7

// Robustly read the stride scalar regardless of dtype (int32/int64 little-endian
// both give the int at offset 0; float32 falls back to float interpretation).
__device__ __forceinline__ float read_stride(const void* p) {
    int iv = *(const int*)p;
    if (iv >= 1 && iv <= 65536) return (float)iv;
    return *(const float*)p;
}

// One block per (roi, py). 256 threads; each thread owns one float4 channel
// chunk. Sliding cache holds Y-PRE-BLENDED columns (one float4 each), so each
// distinct column costs 2 loads + 8 ops once, and each px costs only an x-lerp.
__global__ void __launch_bounds__(256)
roi_pool_kernel(const float* __restrict__ feat,
                const float* __restrict__ rois,
                const void* __restrict__ stride_p,
                float* __restrict__ out,
                int W, int C4) {
    const int py = blockIdx.x;     // 0..6
    const int n  = blockIdx.y;     // roi index

    // ---- uniform per-block coordinate math ----
    const float s = read_stride(stride_p);
    const int ymin = (int)(rois[4 * n + 0] / s);
    const int xmin = (int)(rois[4 * n + 1] / s);
    const int ymax = (int)(rois[4 * n + 2] / s);
    const int xmax = (int)(rois[4 * n + 3] / s);

    // y axis for this py
    const int   spany = ymax - ymin;
    const float sy    = (float)(spany + 1) / (float)POOL;
    const float srcy  = (float)py * sy;
    const int   iy0   = (int)floorf(srcy);
    const float dy    = srcy - (float)iy0;
    const int   iy1   = min(iy0 + 1, spany);
    const int   y0    = ymin + iy0;
    const int   y1    = ymin + iy1;

    // x axis: precompute all 7 sample columns + weights (uniform, unrolled)
    const int   spanx = xmax - xmin;
    const float sx    = (float)(spanx + 1) / (float)POOL;
    int   nx0[POOL], nx1[POOL];
    float dxv[POOL];
#pragma unroll
    for (int px = 0; px < POOL; ++px) {
        const float srcx = (float)px * sx;
        const int   ix0  = (int)floorf(srcx);
        dxv[px] = srcx - (float)ix0;
        nx0[px] = xmin + ix0;
        nx1[px] = xmin + min(ix0 + 1, spanx);
    }

    const float4* __restrict__ f    = (const float4*)feat;
    const float4* __restrict__ row0 = f + y0 * W * C4;   // 32-bit index math
    const float4* __restrict__ row1 = f + y1 * W * C4;
    float4* __restrict__ o = (float4*)out + (n * (POOL * POOL) + py * POOL) * C4;

    for (int c = threadIdx.x; c < C4; c += blockDim.x) {
        // sliding cache of y-blended columns
        int cA = -1, cB = -1;
        float4 vA = make_float4(0.f, 0.f, 0.f, 0.f);
        float4 vB = vA;

#pragma unroll
        for (int px = 0; px < POOL; ++px) {
            const int   x0 = nx0[px];
            const int   x1 = nx1[px];
            const float dx = dxv[px];

            if (x0 != cA) {                    // warp-uniform branches
                if (x0 == cB) { vA = vB; }
                else {
                    const float4 t0 = row0[x0 * C4 + c];
                    const float4 t1 = row1[x0 * C4 + c];
                    vA.x = t0.x + (t1.x - t0.x) * dy;
                    vA.y = t0.y + (t1.y - t0.y) * dy;
                    vA.z = t0.z + (t1.z - t0.z) * dy;
                    vA.w = t0.w + (t1.w - t0.w) * dy;
                }
                cA = x0;
            }
            if (x1 != cB) {
                if (x1 == cA) { vB = vA; }
                else {
                    const float4 t0 = row0[x1 * C4 + c];
                    const float4 t1 = row1[x1 * C4 + c];
                    vB.x = t0.x + (t1.x - t0.x) * dy;
                    vB.y = t0.y + (t1.y - t0.y) * dy;
                    vB.z = t0.z + (t1.z - t0.z) * dy;
                    vB.w = t0.w + (t1.w - t0.w) * dy;
                }
                cB = x1;
            }

            float4 r;
            r.x = vA.x + (vB.x - vA.x) * dx;
            r.y = vA.y + (vB.y - vA.y) * dx;
            r.z = vA.z + (vB.z - vA.z) * dx;
            r.w = vA.w + (vB.w - vA.w) * dx;
            o[px * C4 + c] = r;
        }
    }
}

extern "C" void kernel_launch(void* const* d_in, const int* in_sizes, int n_in,
                              void* d_out, int out_size) {
    const float* feat  = (const float*)d_in[0];   // (1, H, W, C) fp32
    const float* rois  = (const float*)d_in[1];   // (N, 4) fp32
    const void*  strid = d_in[2];                 // scalar

    int N = in_sizes[1] / 4;
    int C = out_size / (N * POOL * POOL);         // 1024
    int HW = in_sizes[0] / C;                     // 4096
    int W = 1;
    while (W * W < HW) W <<= 1;                   // 64 for HW=4096
    if (W * W != HW) {
        W = (int)(sqrtf((float)HW) + 0.5f);       // non-pow2 fallback
    }

    dim3 grid(POOL, N);
    roi_pool_kernel<<<grid, 256>>>(feat, rois, strid, (float*)d_out, W, C / 4);
}